// round 7
// baseline (speedup 1.0000x reference)
#include <cuda_runtime.h>

// Fixed problem shapes
#define BB 64
#define CC 64   // C == Co
#define TT 32
#define NN 64
#define KK 3

#define STRIDE 68               // 64 + 4 pad: float4-aligned
#define BUF (64 * STRIDE)
#define SMEM_FLOATS (2 * BUF + 3 * 64)
#define SMEM_BYTES  (SMEM_FLOATS * 4)     // 35,584 B -> 6 CTAs/SM at 128 thr

typedef unsigned long long u64;

// W transposed once into device-global scratch (WT[c][o] = W[o][c])
__device__ float g_WT[CC * CC];

__global__ void wt_transpose_kernel(const float* __restrict__ W)
{
    const int i = blockIdx.x * 256 + threadIdx.x;   // 0..4095
    const int o = i >> 6;
    const int c = i & 63;
    g_WT[c * CC + o] = W[i];
}

// Packed-f32x2 helpers
#define LDSB64(v, addr)  asm("ld.shared.b64 %0, [%1];" : "=l"(v) : "r"(addr))
#define LDSV2(v0, v1, addr) \
    asm("ld.shared.v2.f32 {%0,%1}, [%2];" : "=f"(v0), "=f"(v1) : "r"(addr))
#define DUP2(d, s)       asm("mov.b64 %0, {%1,%1};" : "=l"(d) : "f"(s))
#define FMA2(d, a, b, c) asm("fma.rn.f32x2 %0, %1, %2, %3;" : "=l"(d) : "l"(a), "l"(b), "l"(c))
#define UNPK2(lo, hi, p) asm("mov.b64 {%0,%1}, %2;" : "=f"(lo), "=f"(hi) : "l"(p))

// One 8x4-tile packed GEMM pass: acc2[ii][j] accumulates output rows
// {8ty+2ii, 8ty+2ii+1}, col 4tx+j.  a from sa (rows = second index),
// b from sb. 16 FMA2 + 4 LDS.b64 + 2 LDS.v2 + 4 dup per iter.
__device__ __forceinline__ void gemm8x4(unsigned sa, unsigned sb,
                                        int tx, int ty, u64 acc[4][4])
{
    #pragma unroll 8
    for (int kk = 0; kk < 64; kk++) {
        const unsigned aad = sa + (unsigned)(kk * STRIDE + ty * 8) * 4u;
        const unsigned bad = sb + (unsigned)(kk * STRIDE + tx * 4) * 4u;
        u64 a2[4];
        LDSB64(a2[0], aad);
        LDSB64(a2[1], aad + 8);
        LDSB64(a2[2], aad + 16);
        LDSB64(a2[3], aad + 24);
        float b0, b1, b2, b3;
        LDSV2(b0, b1, bad);
        LDSV2(b2, b3, bad + 8);
        u64 bd;
        DUP2(bd, b0);
        FMA2(acc[0][0], a2[0], bd, acc[0][0]); FMA2(acc[1][0], a2[1], bd, acc[1][0]);
        FMA2(acc[2][0], a2[2], bd, acc[2][0]); FMA2(acc[3][0], a2[3], bd, acc[3][0]);
        DUP2(bd, b1);
        FMA2(acc[0][1], a2[0], bd, acc[0][1]); FMA2(acc[1][1], a2[1], bd, acc[1][1]);
        FMA2(acc[2][1], a2[2], bd, acc[2][1]); FMA2(acc[3][1], a2[3], bd, acc[3][1]);
        DUP2(bd, b2);
        FMA2(acc[0][2], a2[0], bd, acc[0][2]); FMA2(acc[1][2], a2[1], bd, acc[1][2]);
        FMA2(acc[2][2], a2[2], bd, acc[2][2]); FMA2(acc[3][2], a2[3], bd, acc[3][2]);
        DUP2(bd, b3);
        FMA2(acc[0][3], a2[0], bd, acc[0][3]); FMA2(acc[1][3], a2[1], bd, acc[1][3]);
        FMA2(acc[2][3], a2[2], bd, acc[2][3]); FMA2(acc[3][3], a2[3], bd, acc[3][3]);
    }
}

// One CTA per (b, t). 128 threads. 8x4 register tiles, packed f32x2 FMA.
// s0: x tile [c][n]  -> Asum [n][m]
// s1: WT tile [c][o] -> yT tile [n][o]
// sD: dinv, 3 slabs of 64
__global__ void __launch_bounds__(128, 6)
ctg_kernel(const float* __restrict__ x,
           const float* __restrict__ A,
           const float* __restrict__ bias,
           float* __restrict__ out,
           int copyA)
{
    extern __shared__ float sm[];
    float* s0 = sm;
    float* s1 = sm + BUF;
    float* sD = sm + 2 * BUF;

    const unsigned s0b = (unsigned)__cvta_generic_to_shared(s0);
    const unsigned s1b = (unsigned)__cvta_generic_to_shared(s1);

    const int tid = threadIdx.x;
    const int b   = blockIdx.x / TT;
    const int t   = blockIdx.x % TT;
    const int tx  = tid & 15;   // 4-col group
    const int ty  = tid >> 4;   // 8-row group

    // ---- stage x[b,:,t,:] ([c][n]) and WT ([c][o]) via float4 ----
    #pragma unroll
    for (int it = 0; it < 8; it++) {
        const int e4 = it * 128 + tid;    // float4 slot 0..1023
        const int r  = e4 >> 4;
        const int c4 = e4 & 15;
        *(float4*)(s0 + r * STRIDE + c4 * 4) =
            *(const float4*)(x + (((size_t)(b * CC + r) * TT + t) * NN) + c4 * 4);
        *(float4*)(s1 + r * STRIDE + c4 * 4) =
            *(const float4*)(g_WT + (size_t)e4 * 4);
    }
    __syncthreads();

    // ---- GEMM1: yT[n][o] = sum_c x[c][n] * WT[c][o] + bias[o] ----
    u64 acc[4][4];
    {   // fold bias into accumulator init
        const float4 bia = *(const float4*)(bias + tx * 4);
        u64 bd0, bd1, bd2, bd3;
        DUP2(bd0, bia.x); DUP2(bd1, bia.y); DUP2(bd2, bia.z); DUP2(bd3, bia.w);
        #pragma unroll
        for (int ii = 0; ii < 4; ii++) {
            acc[ii][0] = bd0; acc[ii][1] = bd1; acc[ii][2] = bd2; acc[ii][3] = bd3;
        }
    }
    gemm8x4(s0b, s1b, tx, ty, acc);
    __syncthreads();   // all x/WT reads done before overwriting s1 with yT

    // unpack and store yT rows (8 STS.128)
    #pragma unroll
    for (int ii = 0; ii < 4; ii++) {
        float l0, l1, l2, l3, h0, h1, h2, h3;
        UNPK2(l0, h0, acc[ii][0]); UNPK2(l1, h1, acc[ii][1]);
        UNPK2(l2, h2, acc[ii][2]); UNPK2(l3, h3, acc[ii][3]);
        float4 r0; r0.x = l0; r0.y = l1; r0.z = l2; r0.w = l3;
        float4 r1; r1.x = h0; r1.y = h1; r1.z = h2; r1.w = h3;
        *(float4*)(s1 + (8 * ty + 2 * ii)     * STRIDE + tx * 4) = r0;
        *(float4*)(s1 + (8 * ty + 2 * ii + 1) * STRIDE + tx * 4) = r1;
    }

    // ---- A-phase: register A_k + register Asum, shfl row degrees ----
    float* outA = out + (size_t)BB * CC * TT * NN;

    float4 asum[8];
    #pragma unroll
    for (int it = 0; it < 8; it++) { asum[it].x = asum[it].y = asum[it].z = asum[it].w = 0.0f; }

    const int m0 = tx * 4;

    #pragma unroll
    for (int k = 0; k < KK; k++) {
        const size_t base = (((size_t)b * KK + k) * TT + t) * (size_t)(NN * NN);
        float* sDk = sD + k * 64;

        float4 a[8];
        #pragma unroll
        for (int it = 0; it < 8; it++) {
            const int e4 = it * 128 + tid;
            a[it] = *(const float4*)(A + base + (size_t)e4 * 4);
            if (copyA) *(float4*)(outA + base + (size_t)e4 * 4) = a[it];
        }

        // row degrees: row n = it*8 + ty spans the 16 lanes sharing ty
        #pragma unroll
        for (int it = 0; it < 8; it++) {
            float s = a[it].x + a[it].y + a[it].z + a[it].w;
            s += __shfl_xor_sync(0xffffffffu, s, 1);
            s += __shfl_xor_sync(0xffffffffu, s, 2);
            s += __shfl_xor_sync(0xffffffffu, s, 4);
            s += __shfl_xor_sync(0xffffffffu, s, 8);
            if (tx == 0) sDk[it * 8 + ty] = rsqrtf(s + 1.0f);   // A_tilde = A + I
        }
        __syncthreads();

        const float4 dm = *(const float4*)(sDk + m0);
        #pragma unroll
        for (int it = 0; it < 8; it++) {
            const int n = it * 8 + ty;
            const float dn = sDk[n];
            float4 v = a[it];
            const int d = n - m0;
            if (d == 0) v.x += 1.0f;
            if (d == 1) v.y += 1.0f;
            if (d == 2) v.z += 1.0f;
            if (d == 3) v.w += 1.0f;
            asum[it].x += v.x * dn * dm.x;
            asum[it].y += v.y * dn * dm.y;
            asum[it].z += v.z * dn * dm.z;
            asum[it].w += v.w * dn * dm.w;
        }
        // no trailing sync: next k writes a different sD slab
    }

    // Asum -> s0 (x is dead since post-GEMM1 barrier)
    #pragma unroll
    for (int it = 0; it < 8; it++)
        *(float4*)(s0 + (it * 8 + ty) * STRIDE + m0) = asum[it];
    __syncthreads();

    // ---- GEMM2: x_out[c][m] = sum_n yT[n][c] * Asum[n][m] ----
    u64 acc2[4][4];
    #pragma unroll
    for (int ii = 0; ii < 4; ii++)
        #pragma unroll
        for (int j = 0; j < 4; j++) acc2[ii][j] = 0ull;

    gemm8x4(s1b, s0b, tx, ty, acc2);

    #pragma unroll
    for (int ii = 0; ii < 4; ii++) {
        float l0, l1, l2, l3, h0, h1, h2, h3;
        UNPK2(l0, h0, acc2[ii][0]); UNPK2(l1, h1, acc2[ii][1]);
        UNPK2(l2, h2, acc2[ii][2]); UNPK2(l3, h3, acc2[ii][3]);
        const int c0 = 8 * ty + 2 * ii;
        float4 r0; r0.x = l0; r0.y = l1; r0.z = l2; r0.w = l3;
        float4 r1; r1.x = h0; r1.y = h1; r1.z = h2; r1.w = h3;
        *(float4*)(out + (((size_t)(b * CC + c0)     * TT + t) * NN) + m0) = r0;
        *(float4*)(out + (((size_t)(b * CC + c0 + 1) * TT + t) * NN) + m0) = r1;
    }
}

extern "C" void kernel_launch(void* const* d_in, const int* in_sizes, int n_in,
                              void* d_out, int out_size)
{
    const float* x    = (const float*)d_in[0];
    const float* A    = (const float*)d_in[1];
    const float* W    = (const float*)d_in[2];
    const float* bias = (const float*)d_in[3];
    float* out = (float*)d_out;

    const int xout_elems = BB * CC * TT * NN;           // 8,388,608
    const int copyA = (out_size > xout_elems) ? 1 : 0;  // tuple output (x_out, A)

    wt_transpose_kernel<<<16, 256>>>(W);

    cudaFuncSetAttribute(ctg_kernel, cudaFuncAttributeMaxDynamicSharedMemorySize, SMEM_BYTES);
    ctg_kernel<<<BB * TT, 128, SMEM_BYTES>>>(x, A, bias, out, copyA);
}